// round 7
// baseline (speedup 1.0000x reference)
#include <cuda_runtime.h>
#include <cuda_bf16.h>

// y = (x + 1) * 2/3 ; if y > 0 then y -= 5
// R7: MLP=8 exact-fit. 8192 blocks x 256 threads; each thread handles 8
// float4s within its block's contiguous 32KB chunk (stride 256 float4).
// 8 front-batched LDG.128 per thread, 32 outstanding per warp.

__device__ __forceinline__ float f(float x) {
    const float c = 2.0f / 3.0f;
    float y = fmaf(x, c, c);        // (x+1)*2/3 == x*c + c
    return y > 0.0f ? y - 5.0f : y; // branchless
}

__device__ __forceinline__ float4 f4(float4 a) {
    return make_float4(f(a.x), f(a.y), f(a.z), f(a.w));
}

// Fast path: n4 == 8 * 256 * gridDim.x exactly. Block b owns
// [b*2048, (b+1)*2048) float4s.
__global__ void __launch_bounds__(256, 6) ew_exact8(const float4* __restrict__ in,
                                                    float4* __restrict__ out) {
    int base = blockIdx.x * 2048 + threadIdx.x;
    float4 a0 = in[base];
    float4 a1 = in[base + 256];
    float4 a2 = in[base + 512];
    float4 a3 = in[base + 768];
    float4 a4 = in[base + 1024];
    float4 a5 = in[base + 1280];
    float4 a6 = in[base + 1536];
    float4 a7 = in[base + 1792];
    out[base]        = f4(a0);
    out[base + 256]  = f4(a1);
    out[base + 512]  = f4(a2);
    out[base + 768]  = f4(a3);
    out[base + 1024] = f4(a4);
    out[base + 1280] = f4(a5);
    out[base + 1536] = f4(a6);
    out[base + 1792] = f4(a7);
}

// Generic fallback (any size).
__global__ void __launch_bounds__(256, 8) ew_generic(const float4* __restrict__ in,
                                                     float4* __restrict__ out,
                                                     int n4) {
    int i = blockIdx.x * blockDim.x + threadIdx.x;
    int stride = gridDim.x * blockDim.x;
    for (; i + 3 * stride < n4; i += 4 * stride) {
        float4 a0 = in[i];
        float4 a1 = in[i + stride];
        float4 a2 = in[i + 2 * stride];
        float4 a3 = in[i + 3 * stride];
        out[i]              = f4(a0);
        out[i + stride]     = f4(a1);
        out[i + 2 * stride] = f4(a2);
        out[i + 3 * stride] = f4(a3);
    }
    for (; i < n4; i += stride) {
        out[i] = f4(in[i]);
    }
}

extern "C" void kernel_launch(void* const* d_in, const int* in_sizes, int n_in,
                              void* d_out, int out_size) {
    const float* x = (const float*)d_in[0];
    float* y = (float*)d_out;
    int n = in_sizes[0];          // 67108864
    const int threads = 256;

    if ((n & 3) == 0) {
        int n4 = n >> 2;          // 16777216
        if ((n4 & 2047) == 0) {   // exact multiple of 2048 float4 per block
            int blocks = n4 >> 11;             // 8192
            ew_exact8<<<blocks, threads>>>((const float4*)x, (float4*)y);
            return;
        }
        ew_generic<<<148 * 8 * 4, threads>>>((const float4*)x, (float4*)y, n4);
        return;
    }
    ew_generic<<<148 * 8 * 4, threads>>>((const float4*)x, (float4*)y, n / 4);
}

// round 8
// speedup vs baseline: 1.0004x; 1.0004x over previous
#include <cuda_runtime.h>
#include <cuda_bf16.h>

// y = (x + 1) * 2/3 ; if y > 0 then y -= 5
// R8 (final form): CTA-contiguous exact-fit, MLP=4 per thread, paired
// ld/ld/st/st to start the write stream draining one load-latency earlier.
// 16384 blocks x 256 threads; block b owns float4s [b*1024, (b+1)*1024).

__device__ __forceinline__ float f(float x) {
    const float c = 2.0f / 3.0f;
    float y = fmaf(x, c, c);        // (x+1)*2/3 == x*c + c
    return y > 0.0f ? y - 5.0f : y; // branchless
}

__device__ __forceinline__ float4 f4(float4 a) {
    return make_float4(f(a.x), f(a.y), f(a.z), f(a.w));
}

__global__ void __launch_bounds__(256, 8) ew_exact(const float4* __restrict__ in,
                                                   float4* __restrict__ out) {
    int base = blockIdx.x * 1024 + threadIdx.x;
    float4 a0 = in[base];
    float4 a1 = in[base + 256];
    out[base]       = f4(a0);
    out[base + 256] = f4(a1);
    float4 a2 = in[base + 512];
    float4 a3 = in[base + 768];
    out[base + 512] = f4(a2);
    out[base + 768] = f4(a3);
}

// Generic fallback (any size).
__global__ void __launch_bounds__(256, 8) ew_generic(const float4* __restrict__ in,
                                                     float4* __restrict__ out,
                                                     int n4) {
    int i = blockIdx.x * blockDim.x + threadIdx.x;
    int stride = gridDim.x * blockDim.x;
    for (; i + 3 * stride < n4; i += 4 * stride) {
        float4 a0 = in[i];
        float4 a1 = in[i + stride];
        float4 a2 = in[i + 2 * stride];
        float4 a3 = in[i + 3 * stride];
        out[i]              = f4(a0);
        out[i + stride]     = f4(a1);
        out[i + 2 * stride] = f4(a2);
        out[i + 3 * stride] = f4(a3);
    }
    for (; i < n4; i += stride) {
        out[i] = f4(in[i]);
    }
}

extern "C" void kernel_launch(void* const* d_in, const int* in_sizes, int n_in,
                              void* d_out, int out_size) {
    const float* x = (const float*)d_in[0];
    float* y = (float*)d_out;
    int n = in_sizes[0];          // 67108864
    const int threads = 256;

    if ((n & 3) == 0) {
        int n4 = n >> 2;          // 16777216
        if ((n4 & 1023) == 0) {   // exact multiple of 1024 float4 per block
            int blocks = n4 >> 10;             // 16384
            ew_exact<<<blocks, threads>>>((const float4*)x, (float4*)y);
            return;
        }
        ew_generic<<<148 * 8 * 4, threads>>>((const float4*)x, (float4*)y, n4);
        return;
    }
    ew_generic<<<148 * 8 * 4, threads>>>((const float4*)x, (float4*)y, n / 4);
}

// round 9
// speedup vs baseline: 1.0047x; 1.0043x over previous
#include <cuda_runtime.h>
#include <cuda_bf16.h>

// y = (x + 1) * 2/3 ; if y > 0 then y -= 5
// R9: confirmation probe on CTA size. Same roofline structure as R8
// (CTA-contiguous, MLP=4/thread, exact-fit, 24-reg class) but 512-thread
// CTAs: 8192 blocks, block b owns float4s [b*2048, (b+1)*2048).

__device__ __forceinline__ float f(float x) {
    const float c = 2.0f / 3.0f;
    float y = fmaf(x, c, c);        // (x+1)*2/3 == x*c + c
    return y > 0.0f ? y - 5.0f : y; // branchless
}

__device__ __forceinline__ float4 f4(float4 a) {
    return make_float4(f(a.x), f(a.y), f(a.z), f(a.w));
}

__global__ void __launch_bounds__(512, 4) ew_exact(const float4* __restrict__ in,
                                                   float4* __restrict__ out) {
    int base = blockIdx.x * 2048 + threadIdx.x;
    float4 a0 = in[base];
    float4 a1 = in[base + 512];
    out[base]        = f4(a0);
    out[base + 512]  = f4(a1);
    float4 a2 = in[base + 1024];
    float4 a3 = in[base + 1536];
    out[base + 1024] = f4(a2);
    out[base + 1536] = f4(a3);
}

// Generic fallback (any size).
__global__ void __launch_bounds__(256, 8) ew_generic(const float4* __restrict__ in,
                                                     float4* __restrict__ out,
                                                     int n4) {
    int i = blockIdx.x * blockDim.x + threadIdx.x;
    int stride = gridDim.x * blockDim.x;
    for (; i + 3 * stride < n4; i += 4 * stride) {
        float4 a0 = in[i];
        float4 a1 = in[i + stride];
        float4 a2 = in[i + 2 * stride];
        float4 a3 = in[i + 3 * stride];
        out[i]              = f4(a0);
        out[i + stride]     = f4(a1);
        out[i + 2 * stride] = f4(a2);
        out[i + 3 * stride] = f4(a3);
    }
    for (; i < n4; i += stride) {
        out[i] = f4(in[i]);
    }
}

extern "C" void kernel_launch(void* const* d_in, const int* in_sizes, int n_in,
                              void* d_out, int out_size) {
    const float* x = (const float*)d_in[0];
    float* y = (float*)d_out;
    int n = in_sizes[0];          // 67108864
    const int threads = 512;

    if ((n & 3) == 0) {
        int n4 = n >> 2;          // 16777216
        if ((n4 & 2047) == 0) {   // exact multiple of 2048 float4 per block
            int blocks = n4 >> 11;             // 8192
            ew_exact<<<blocks, threads>>>((const float4*)x, (float4*)y);
            return;
        }
        ew_generic<<<148 * 8 * 4, 256>>>((const float4*)x, (float4*)y, n4);
        return;
    }
    ew_generic<<<148 * 8 * 4, 256>>>((const float4*)x, (float4*)y, n / 4);
}

// round 10
// speedup vs baseline: 1.0055x; 1.0008x over previous
#include <cuda_runtime.h>
#include <cuda_bf16.h>

// y = (x + 1) * 2/3 ; if y > 0 then y -= 5
// FINAL (R8 form, best measured: kernel 74.40us, DRAM 81.8%, 6.48 TB/s):
// CTA-contiguous exact-fit, MLP=4 per thread, paired ld/ld/st/st.
// 16384 blocks x 256 threads; block b owns float4s [b*1024, (b+1)*1024).
// Roofline-limited: 512MB mandatory traffic / ~6.48 TB/s achieved mixed
// R/W HBM ceiling. No further kernel-side lever exists (verified over
// unroll, grid, CTA size, cache hints, layout, ordering).

__device__ __forceinline__ float f(float x) {
    const float c = 2.0f / 3.0f;
    float y = fmaf(x, c, c);        // (x+1)*2/3 == x*c + c
    return y > 0.0f ? y - 5.0f : y; // branchless
}

__device__ __forceinline__ float4 f4(float4 a) {
    return make_float4(f(a.x), f(a.y), f(a.z), f(a.w));
}

__global__ void __launch_bounds__(256, 8) ew_exact(const float4* __restrict__ in,
                                                   float4* __restrict__ out) {
    int base = blockIdx.x * 1024 + threadIdx.x;
    float4 a0 = in[base];
    float4 a1 = in[base + 256];
    out[base]       = f4(a0);
    out[base + 256] = f4(a1);
    float4 a2 = in[base + 512];
    float4 a3 = in[base + 768];
    out[base + 512] = f4(a2);
    out[base + 768] = f4(a3);
}

// Generic fallback (any size).
__global__ void __launch_bounds__(256, 8) ew_generic(const float4* __restrict__ in,
                                                     float4* __restrict__ out,
                                                     int n4) {
    int i = blockIdx.x * blockDim.x + threadIdx.x;
    int stride = gridDim.x * blockDim.x;
    for (; i + 3 * stride < n4; i += 4 * stride) {
        float4 a0 = in[i];
        float4 a1 = in[i + stride];
        float4 a2 = in[i + 2 * stride];
        float4 a3 = in[i + 3 * stride];
        out[i]              = f4(a0);
        out[i + stride]     = f4(a1);
        out[i + 2 * stride] = f4(a2);
        out[i + 3 * stride] = f4(a3);
    }
    for (; i < n4; i += stride) {
        out[i] = f4(in[i]);
    }
}

extern "C" void kernel_launch(void* const* d_in, const int* in_sizes, int n_in,
                              void* d_out, int out_size) {
    const float* x = (const float*)d_in[0];
    float* y = (float*)d_out;
    int n = in_sizes[0];          // 67108864
    const int threads = 256;

    if ((n & 3) == 0) {
        int n4 = n >> 2;          // 16777216
        if ((n4 & 1023) == 0) {   // exact multiple of 1024 float4 per block
            int blocks = n4 >> 10;             // 16384
            ew_exact<<<blocks, threads>>>((const float4*)x, (float4*)y);
            return;
        }
        ew_generic<<<148 * 8 * 4, threads>>>((const float4*)x, (float4*)y, n4);
        return;
    }
    ew_generic<<<148 * 8 * 4, threads>>>((const float4*)x, (float4*)y, n / 4);
}